// round 4
// baseline (speedup 1.0000x reference)
#include <cuda_runtime.h>
#include <math.h>

#define Bb 4
#define Ll 4096
#define Hh 1024
#define Mm 4096          // complex FFT size (packs 8192 reals)
#define ABSTRIDE 4112    // float4 per head for coeffs: 2 per k, k=0..2048, padded

__device__ __align__(16) float g_xt[(size_t)Bb * Hh * Ll];
__device__ __align__(16) float4 g_AB[(size_t)Hh * ABSTRIDE];

__device__ __forceinline__ int pad16(int i) { return i + (i >> 4); }
#define SBUF_N 4352      // > pad16(4095)+1 = 4351

__device__ __forceinline__ float2 cadd(float2 a, float2 b) { return make_float2(a.x + b.x, a.y + b.y); }
__device__ __forceinline__ float2 csub(float2 a, float2 b) { return make_float2(a.x - b.x, a.y - b.y); }
__device__ __forceinline__ float2 cmul(float2 a, float2 b) {
    return make_float2(a.x * b.x - a.y * b.y, a.x * b.y + a.y * b.x);
}
__device__ __forceinline__ float2 mnegi(float2 a) { return make_float2(a.y, -a.x); }  // * -i

template <int Ns>
__device__ __forceinline__ float2 tw_base(int t) {
    int j = t & (Ns - 1);
    float sn, cs;
    sincospif((float)j * (1.0f / (4.0f * (float)Ns)), &sn, &cs);
    return make_float2(cs, -sn);
}

__device__ __forceinline__ void twiddle8(float2 v[8], float2 w1) {
    float2 w = w1;
    v[1] = cmul(v[1], w);
#pragma unroll
    for (int r = 2; r < 8; ++r) { w = cmul(w, w1); v[r] = cmul(v[r], w); }
}

__device__ __forceinline__ void fft8_tail(float2 v[8],
        float2 E0, float2 E1, float2 E2, float2 E3,
        float2 O0, float2 O1, float2 O2, float2 O3) {
    const float s = 0.70710678118654752440f;
    float2 W1 = make_float2(s * (O1.x + O1.y), s * (O1.y - O1.x));
    float2 W2 = mnegi(O2);
    float2 W3 = make_float2(s * (O3.y - O3.x), -s * (O3.x + O3.y));
    v[0] = cadd(E0, O0); v[4] = csub(E0, O0);
    v[1] = cadd(E1, W1); v[5] = csub(E1, W1);
    v[2] = cadd(E2, W2); v[6] = csub(E2, W2);
    v[3] = cadd(E3, W3); v[7] = csub(E3, W3);
}

__device__ __forceinline__ void fft8(float2 v[8]) {
    float2 e0a = cadd(v[0], v[4]), e0b = csub(v[0], v[4]);
    float2 e1a = cadd(v[2], v[6]), e1b = csub(v[2], v[6]);
    float2 E0 = cadd(e0a, e1a), E2 = csub(e0a, e1a);
    float2 m1 = mnegi(e1b);
    float2 E1 = cadd(e0b, m1), E3 = csub(e0b, m1);
    float2 o0a = cadd(v[1], v[5]), o0b = csub(v[1], v[5]);
    float2 o1a = cadd(v[3], v[7]), o1b = csub(v[3], v[7]);
    float2 O0 = cadd(o0a, o1a), O2 = csub(o0a, o1a);
    float2 m2 = mnegi(o1b);
    float2 O1 = cadd(o0b, m2), O3 = csub(o0b, m2);
    fft8_tail(v, E0, E1, E2, E3, O0, O1, O2, O3);
}

// radix-8 butterfly with v[4..7] == 0
__device__ __forceinline__ void fft8h(float2 v[8]) {
    float2 E0 = cadd(v[0], v[2]), E2 = csub(v[0], v[2]);
    float2 m1 = mnegi(v[2]);
    float2 E1 = cadd(v[0], m1), E3 = csub(v[0], m1);
    float2 O0 = cadd(v[1], v[3]), O2 = csub(v[1], v[3]);
    float2 m2 = mnegi(v[3]);
    float2 O1 = cadd(v[1], m2), O3 = csub(v[1], m2);
    fft8_tail(v, E0, E1, E2, E3, O0, O1, O2, O3);
}

// ---------------- radix-16 building blocks (kmain) ----------------
// 16-pt DFT, natural in/out, via even/odd split over fft8
__device__ __forceinline__ void fft16_core(float2 v[16], bool halfzero) {
    float2 e[8], o[8];
#pragma unroll
    for (int r = 0; r < 8; ++r) { e[r] = v[2 * r]; o[r] = v[2 * r + 1]; }
    if (halfzero) { fft8h(e); fft8h(o); } else { fft8(e); fft8(o); }
    const float c1 = 0.92387953251128675613f;  // cos(pi/8)
    const float s1 = 0.38268343236508977173f;  // sin(pi/8)
    const float s2 = 0.70710678118654752440f;
    float2 t;
    v[0] = cadd(e[0], o[0]);                       v[8]  = csub(e[0], o[0]);
    t = cmul(o[1], make_float2( c1, -s1)); v[1] = cadd(e[1], t); v[9]  = csub(e[1], t);
    t = cmul(o[2], make_float2( s2, -s2)); v[2] = cadd(e[2], t); v[10] = csub(e[2], t);
    t = cmul(o[3], make_float2( s1, -c1)); v[3] = cadd(e[3], t); v[11] = csub(e[3], t);
    t = mnegi(o[4]);                       v[4] = cadd(e[4], t); v[12] = csub(e[4], t);
    t = cmul(o[5], make_float2(-s1, -c1)); v[5] = cadd(e[5], t); v[13] = csub(e[5], t);
    t = cmul(o[6], make_float2(-s2, -s2)); v[6] = cadd(e[6], t); v[14] = csub(e[6], t);
    t = cmul(o[7], make_float2(-c1, -s1)); v[7] = cadd(e[7], t); v[15] = csub(e[7], t);
}

// v[r] *= w1^r, two chains (odd/even powers) to halve dependency depth
__device__ __forceinline__ void twiddle16(float2 v[16], float2 w1) {
    float2 w2 = cmul(w1, w1);
    float2 wo = w1, we = w2;
    v[1] = cmul(v[1], wo);
    v[2] = cmul(v[2], we);
#pragma unroll
    for (int r = 3; r < 16; r += 2) {
        wo = cmul(wo, w2); v[r] = cmul(v[r], wo);
        if (r + 1 < 16) { we = cmul(we, w2); v[r + 1] = cmul(v[r + 1], we); }
    }
}

template <int Ns>
__device__ __forceinline__ void exch16(float2 v[16], int t, float2* s) {
    int idxD = ((t & ~(Ns - 1)) << 4) | (t & (Ns - 1));
#pragma unroll
    for (int r = 0; r < 16; ++r) s[pad16(idxD + r * Ns)] = v[r];
    __syncthreads();
#pragma unroll
    for (int r = 0; r < 16; ++r) v[r] = s[pad16(t + (r << 8))];
    __syncthreads();
}

// 4096-pt FFT, radix-16, 256 threads. Exit: v[r] = Z[t + 256 r] (natural)
__device__ __forceinline__ void fft4096_r16(float2 v[16], int t, float2* s,
                                            float2 wA, float2 wB, bool halfzero) {
    fft16_core(v, halfzero);
    exch16<1>(v, t, s);
    twiddle16(v, wA); fft16_core(v, false);
    exch16<16>(v, t, s);
    twiddle16(v, wB); fft16_core(v, false);
}

// ---------------- radix-8 pipeline (kfront only) ----------------
template <int Ns>
__device__ __forceinline__ void exch(float2 v[8], int t, float2* s) {
    int idxD = ((t & ~(Ns - 1)) << 3) | (t & (Ns - 1));
#pragma unroll
    for (int r = 0; r < 8; ++r) s[pad16(idxD + r * Ns)] = v[r];
    __syncthreads();
#pragma unroll
    for (int r = 0; r < 8; ++r) v[r] = s[pad16(t + (r << 9))];
    __syncthreads();
}

__device__ __forceinline__ void fft4096_reg(float2 v[8], int t, float2* s,
                                            float2 w8, float2 w64, float2 w512, bool halfzero) {
    if (halfzero) fft8h(v); else fft8(v);
    exch<1>(v, t, s);
    twiddle8(v, w8);  fft8(v); exch<8>(v, t, s);
    twiddle8(v, w64); fft8(v); exch<64>(v, t, s);
    twiddle8(v, w512); fft8(v);
}

__device__ __forceinline__ void store_natural(const float2 v[8], int t, float2* s) {
#pragma unroll
    for (int r = 0; r < 8; ++r) s[pad16(t + (r << 9))] = v[r];
    __syncthreads();
}

// From K's packed FFT (in smem), compute the 4 middle-coefficients for frequency k:
//   C[k] = conj(a1) conj(Zk) + conj(b1) Zm ;  C[M-k] = a2 Zk + b2 conj(Zm)
__device__ __forceinline__ void ab_step(int k, float uc, float us,
                                        const float2* s, float4* __restrict__ outp) {
    int km = (Mm - k) & (Mm - 1);
    float2 Zk = s[pad16(k)];
    float2 Zm = s[pad16(km)];
    float2 Fe = make_float2(0.5f * (Zk.x + Zm.x), 0.5f * (Zk.y - Zm.y));
    float2 Fo = make_float2(0.5f * (Zk.y + Zm.y), -0.5f * (Zk.x - Zm.x));
    float2 P  = make_float2(uc * Fo.x + us * Fo.y, uc * Fo.y - us * Fo.x);  // u*Fo, u=(uc,-us)
    float2 Kk  = cadd(Fe, P);          // K spectrum at k
    float2 Kbm = csub(Fe, P);          // conj(K spectrum at M-k)
    float2 p  = make_float2(-0.5f * us, -0.5f * uc);   // p = -i*u/2
    float2 S  = make_float2(0.5f + p.x,  p.y);
    float2 T  = make_float2(0.5f - p.x, -p.y);
    float2 KkS = cmul(Kk, S),  KbT = cmul(Kbm, T);
    float2 KkT = cmul(Kk, T),  KbS = cmul(Kbm, S);
    float2 G1 = make_float2(0.5f * (KkS.x + KbT.x), 0.5f * (KkS.y + KbT.y));
    float2 H1r = make_float2(0.5f * (KkS.x - KbT.x), 0.5f * (KkS.y - KbT.y));
    float2 G2 = make_float2(0.5f * (KkT.x + KbS.x), 0.5f * (KkT.y + KbS.y));
    float2 H2r = make_float2(0.5f * (KkT.x - KbS.x), 0.5f * (KkT.y - KbS.y));
    float2 iu = make_float2(-us, uc);  // i * conj(u)
    float2 H1 = cmul(iu, H1r);
    float2 H2 = cmul(iu, H2r);
    float2 a1 = cadd(G1, H1), a2 = csub(G1, H1);
    float2 b1 = cadd(G2, H2), b2 = csub(G2, H2);
    outp[2 * k]     = make_float4(a1.x, -a1.y, b1.x, -b1.y);  // conj(a1), conj(b1)
    outp[2 * k + 1] = make_float4(a2.x,  a2.y, b2.x,  b2.y);
}

// ---- 64x64 float4 transpose tile with XOR swizzle ----
__device__ __forceinline__ void trans_tile(const float* __restrict__ src, float* __restrict__ dst,
                                           int ldS, int ldD, int r0, int c0,
                                           int u, int step, float4* tile) {
    int c = u & 15;
    for (int l = u >> 4; l < 64; l += step) {
        const float4* p = (const float4*)(src + (size_t)(r0 + l) * ldS + c0) + c;
        tile[l * 16 + (c ^ (l >> 2))] = *p;
    }
    __syncthreads();
    const float* ts = (const float*)tile;
    int l4 = u & 15;
    for (int h = u >> 4; h < 64; h += step) {
        int col = (h >> 2) ^ l4;
        int base = l4 * 64;
        float4 o;
        o.x = ts[(base + col) * 4 + (h & 3)];
        o.y = ts[(base + 16 + col) * 4 + (h & 3)];
        o.z = ts[(base + 32 + col) * 4 + (h & 3)];
        o.w = ts[(base + 48 + col) * 4 + (h & 3)];
        *((float4*)(dst + (size_t)(c0 + h) * ldD + r0) + l4) = o;
    }
}

__global__ void kdummy() {}

// ---------------- Kernel 1: K coeff precompute + input transpose ----------------
__global__ void __launch_bounds__(512) kfront(const float* __restrict__ x,
                                              const float* __restrict__ kin) {
    __shared__ __align__(16) float2 sbuf[SBUF_N];
    int t = threadIdx.x;
    if (blockIdx.x < Hh) {
        int h = blockIdx.x;
        float2 w8 = tw_base<8>(t), w64 = tw_base<64>(t), w512 = tw_base<512>(t);
        float uc[4], us[4];
#pragma unroll
        for (int i = 0; i < 4; ++i)
            sincospif((float)(t + (i << 9)) * (1.0f / 4096.0f), &us[i], &uc[i]);
        const float2* row = (const float2*)(kin + (size_t)h * Ll);
        float2 v[8];
#pragma unroll
        for (int r = 0; r < 4; ++r) {
            float2 a = row[t + (r << 9)];
            a.x = copysignf(fmaxf(fabsf(a.x) - 0.1f, 0.0f), a.x);
            a.y = copysignf(fmaxf(fabsf(a.y) - 0.1f, 0.0f), a.y);
            v[r] = a;
        }
#pragma unroll
        for (int r = 4; r < 8; ++r) v[r] = make_float2(0.0f, 0.0f);
        fft4096_reg(v, t, sbuf, w8, w64, w512, true);
        store_natural(v, t, sbuf);
        float4* outp = g_AB + (size_t)h * ABSTRIDE;
#pragma unroll
        for (int i = 0; i < 4; ++i)
            ab_step(t + (i << 9), uc[i], us[i], sbuf, outp);
        if (t == 0) ab_step(2048, 0.0f, 1.0f, sbuf, outp);
    } else {
        int bid = blockIdx.x - Hh;
        int b = bid >> 10;
        int rem = bid & 1023;
        int l0 = (rem >> 4) << 6;
        int h0 = (rem & 15) << 6;
        float4* tile = (float4*)sbuf;
        trans_tile(x + (size_t)b * Ll * Hh, g_xt + (size_t)b * Hh * Ll,
                   Hh, Ll, l0, h0, t, 32, tile);
    }
}

// ---------------- Kernel 2: per-(b,h) FFT convolution, radix-16 ----------------
__global__ void __launch_bounds__(256, 2) kmain() {
    __shared__ __align__(16) float2 sbuf[SBUF_N];
    int row = blockIdx.x;            // b*H + h
    int h = row & (Hh - 1);
    int t = threadIdx.x;             // 0..255
    float snA, csA, snB, csB;
    sincospif((float)(t & 15) * (1.0f / 128.0f), &snA, &csA);   // exp(-2pi i j/256)
    sincospif((float)t * (1.0f / 2048.0f), &snB, &csB);         // exp(-2pi i t/4096)
    float2 wA = make_float2(csA, -snA), wB = make_float2(csB, -snB);
    const float4* AB = g_AB + (size_t)h * ABSTRIDE;
    float2* xrow = ((float2*)g_xt) + (size_t)row * (Ll / 2);

    float2 v[16];
#pragma unroll
    for (int r = 0; r < 8; ++r) v[r] = xrow[t + (r << 8)];      // z[n] = x[2n] + i x[2n+1]
#pragma unroll
    for (int r = 8; r < 16; ++r) v[r] = make_float2(0.0f, 0.0f);
    fft4096_r16(v, t, sbuf, wA, wB, true);    // regs: v[r] = Z[t + 256 r]

    // publish upper half of Z (positions 2048..4095) + Z[0] from thread 0
#pragma unroll
    for (int r = 8; r < 16; ++r) sbuf[pad16(t + (r << 8))] = v[r];
    if (t == 0) sbuf[0] = v[0];
    __syncthreads();

    // middle: per task i, k = t + 256 i in [0, 2047]; Zk in regs, Zm from smem.
    // Each smem slot m is read (Zm) then written (C[m]) by the SAME thread.
#pragma unroll
    for (int i = 0; i < 8; ++i) {
        int k = t + (i << 8);
        int m = (Mm - k) & (Mm - 1);
        float2 Zk = v[i];
        float2 Zm = sbuf[pad16(m)];
        float4 cA = __ldg(&AB[2 * k]);       // conj(a1).x/.y, conj(b1).z/.w
        float4 cB = __ldg(&AB[2 * k + 1]);   // a2, b2
        float2 Ck, Cm;
        Ck.x = cA.x * Zk.x + cA.y * Zk.y + cA.z * Zm.x - cA.w * Zm.y;
        Ck.y = cA.y * Zk.x - cA.x * Zk.y + cA.z * Zm.y + cA.w * Zm.x;
        Cm.x = cB.x * Zk.x - cB.y * Zk.y + cB.z * Zm.x + cB.w * Zm.y;
        Cm.y = cB.x * Zk.y + cB.y * Zk.x - cB.z * Zm.y + cB.w * Zm.x;
        v[i] = Ck;                            // C[k] stays in-register for inverse
        if (k != 0) sbuf[pad16(m)] = Cm;      // C[4096-k], m in 2048..4095
    }
    if (t == 0) {                             // k = 2048 (Nyquist of packed FFT)
        float2 Z = sbuf[pad16(2048)];
        float4 cA = __ldg(&AB[2 * 2048]);
        float2 Ck;
        Ck.x = cA.x * Z.x + cA.y * Z.y + cA.z * Z.x - cA.w * Z.y;
        Ck.y = cA.y * Z.x - cA.x * Z.y + cA.z * Z.y + cA.w * Z.x;
        sbuf[pad16(2048)] = Ck;
    }
    __syncthreads();

    // gather upper half of C; lower half already in v[0..7]
#pragma unroll
    for (int r = 8; r < 16; ++r) v[r] = sbuf[pad16(t + (r << 8))];
    __syncthreads();

    // inverse via conj trick: y-packed = conj(FFT(C))/M
    fft4096_r16(v, t, sbuf, wA, wB, false);
    const float invM = 1.0f / 4096.0f;
#pragma unroll
    for (int r = 0; r < 8; ++r) {             // first 4096 reals = 2048 complex
        int p = t + (r << 8);
        xrow[p] = make_float2(v[r].x * invM, -v[r].y * invM);
    }
}

// ---------------- Kernel 3: transpose yt -> out, fused D*x skip ----------------
__global__ void __launch_bounds__(256) ktrans_out(const float* __restrict__ x,
                                                  const float* __restrict__ Dv,
                                                  float* __restrict__ out) {
    __shared__ __align__(16) float4 tile[1024];
    int b = blockIdx.z;
    int h0 = blockIdx.x << 6, l0 = blockIdx.y << 6;
    const float* src = g_xt + (size_t)b * Hh * Ll;
    int u = threadIdx.x;
    int c = u & 15;
    for (int l = u >> 4; l < 64; l += 16) {
        const float4* p = (const float4*)(src + (size_t)(h0 + l) * Ll + l0) + c;
        tile[l * 16 + (c ^ (l >> 2))] = *p;
    }
    __syncthreads();
    const float* ts = (const float*)tile;
    int l4 = u & 15;
    float4 d = ((const float4*)Dv)[(h0 >> 2) + l4];
    const float* xb = x + (size_t)b * Ll * Hh;
    float* ob = out + (size_t)b * Ll * Hh;
    for (int lh = u >> 4; lh < 64; lh += 16) {
        int col = (lh >> 2) ^ l4;
        int base = l4 * 64;
        float4 o;
        o.x = ts[(base + col) * 4 + (lh & 3)];
        o.y = ts[(base + 16 + col) * 4 + (lh & 3)];
        o.z = ts[(base + 32 + col) * 4 + (lh & 3)];
        o.w = ts[(base + 48 + col) * 4 + (lh & 3)];
        size_t off = (size_t)(l0 + lh) * Hh + h0;
        float4 xv = *((const float4*)(xb + off) + l4);
        o.x = fmaf(d.x, xv.x, o.x);
        o.y = fmaf(d.y, xv.y, o.y);
        o.z = fmaf(d.z, xv.z, o.z);
        o.w = fmaf(d.w, xv.w, o.w);
        *((float4*)(ob + off) + l4) = o;
    }
}

extern "C" void kernel_launch(void* const* d_in, const int* in_sizes, int n_in,
                              void* d_out, int out_size) {
    const float* x   = (const float*)d_in[0];
    const float* ker = (const float*)d_in[1];
    const float* Dv  = (const float*)d_in[2];
    for (int i = 0; i < n_in; ++i) {
        if (in_sizes[i] == Bb * Ll * Hh)      x   = (const float*)d_in[i];
        else if (in_sizes[i] == Hh * Ll)      ker = (const float*)d_in[i];
        else if (in_sizes[i] == Hh)           Dv  = (const float*)d_in[i];
    }
    kdummy<<<1, 32>>>();
    kdummy<<<1, 32>>>();
    kfront<<<Hh + (Bb * (Ll / 64) * (Hh / 64)), 512>>>(x, ker);
    kmain<<<Bb * Hh, 256>>>();
    ktrans_out<<<dim3(Hh / 64, Ll / 64, Bb), 256>>>(x, Dv, (float*)d_out);
}

// round 5
// speedup vs baseline: 1.0830x; 1.0830x over previous
#include <cuda_runtime.h>
#include <math.h>

#define Bb 4
#define Ll 4096
#define Hh 1024
#define Mm 4096          // complex FFT size (packs 8192 reals)
#define KPSTRIDE 2056    // float4 per head: (K[k], K[M-k]) for k=0..2048, padded

__device__ __align__(16) float g_xt[(size_t)Bb * Hh * Ll];
__device__ __align__(16) float4 g_KP[(size_t)Hh * KPSTRIDE];

__device__ __forceinline__ int pad16(int i) { return i + (i >> 4); }
#define SBUF_N 4352      // > pad16(4095)+1 = 4351

__device__ __forceinline__ float2 cadd(float2 a, float2 b) { return make_float2(a.x + b.x, a.y + b.y); }
__device__ __forceinline__ float2 csub(float2 a, float2 b) { return make_float2(a.x - b.x, a.y - b.y); }
__device__ __forceinline__ float2 cmul(float2 a, float2 b) {
    return make_float2(a.x * b.x - a.y * b.y, a.x * b.y + a.y * b.x);
}
__device__ __forceinline__ float2 mnegi(float2 a) { return make_float2(a.y, -a.x); }  // * -i

template <int Ns>
__device__ __forceinline__ float2 tw_base(int t) {
    int j = t & (Ns - 1);
    float sn, cs;
    sincospif((float)j * (1.0f / (4.0f * (float)Ns)), &sn, &cs);
    return make_float2(cs, -sn);
}

__device__ __forceinline__ void twiddle8(float2 v[8], float2 w1) {
    float2 w = w1;
    v[1] = cmul(v[1], w);
#pragma unroll
    for (int r = 2; r < 8; ++r) { w = cmul(w, w1); v[r] = cmul(v[r], w); }
}

__device__ __forceinline__ void fft8_tail(float2 v[8],
        float2 E0, float2 E1, float2 E2, float2 E3,
        float2 O0, float2 O1, float2 O2, float2 O3) {
    const float s = 0.70710678118654752440f;
    float2 W1 = make_float2(s * (O1.x + O1.y), s * (O1.y - O1.x));
    float2 W2 = mnegi(O2);
    float2 W3 = make_float2(s * (O3.y - O3.x), -s * (O3.x + O3.y));
    v[0] = cadd(E0, O0); v[4] = csub(E0, O0);
    v[1] = cadd(E1, W1); v[5] = csub(E1, W1);
    v[2] = cadd(E2, W2); v[6] = csub(E2, W2);
    v[3] = cadd(E3, W3); v[7] = csub(E3, W3);
}

__device__ __forceinline__ void fft8(float2 v[8]) {
    float2 e0a = cadd(v[0], v[4]), e0b = csub(v[0], v[4]);
    float2 e1a = cadd(v[2], v[6]), e1b = csub(v[2], v[6]);
    float2 E0 = cadd(e0a, e1a), E2 = csub(e0a, e1a);
    float2 m1 = mnegi(e1b);
    float2 E1 = cadd(e0b, m1), E3 = csub(e0b, m1);
    float2 o0a = cadd(v[1], v[5]), o0b = csub(v[1], v[5]);
    float2 o1a = cadd(v[3], v[7]), o1b = csub(v[3], v[7]);
    float2 O0 = cadd(o0a, o1a), O2 = csub(o0a, o1a);
    float2 m2 = mnegi(o1b);
    float2 O1 = cadd(o0b, m2), O3 = csub(o0b, m2);
    fft8_tail(v, E0, E1, E2, E3, O0, O1, O2, O3);
}

// radix-8 butterfly with v[4..7] == 0 (zero-padded input, first pass only)
__device__ __forceinline__ void fft8h(float2 v[8]) {
    float2 E0 = cadd(v[0], v[2]), E2 = csub(v[0], v[2]);
    float2 m1 = mnegi(v[2]);
    float2 E1 = cadd(v[0], m1), E3 = csub(v[0], m1);
    float2 O0 = cadd(v[1], v[3]), O2 = csub(v[1], v[3]);
    float2 m2 = mnegi(v[3]);
    float2 O1 = cadd(v[1], m2), O3 = csub(v[1], m2);
    fft8_tail(v, E0, E1, E2, E3, O0, O1, O2, O3);
}

// inter-pass exchange through float2 smem (digit-reversal scatter, natural gather)
template <int Ns>
__device__ __forceinline__ void exch(float2 v[8], int t, float2* s) {
    int idxD = ((t & ~(Ns - 1)) << 3) | (t & (Ns - 1));
#pragma unroll
    for (int r = 0; r < 8; ++r) s[pad16(idxD + r * Ns)] = v[r];
    __syncthreads();
#pragma unroll
    for (int r = 0; r < 8; ++r) v[r] = s[pad16(t + (r << 9))];
    __syncthreads();
}

// 4096-pt FFT. Last pass's exchange is identity -> regs end natural: v[r] = Z[t+512r]
__device__ __forceinline__ void fft4096_reg(float2 v[8], int t, float2* s,
                                            float2 w8, float2 w64, float2 w512, bool halfzero) {
    if (halfzero) fft8h(v); else fft8(v);
    exch<1>(v, t, s);
    twiddle8(v, w8);  fft8(v); exch<8>(v, t, s);
    twiddle8(v, w64); fft8(v); exch<64>(v, t, s);
    twiddle8(v, w512); fft8(v);
}

__device__ __forceinline__ void store_natural(const float2 v[8], int t, float2* s) {
#pragma unroll
    for (int r = 0; r < 8; ++r) s[pad16(t + (r << 9))] = v[r];
    __syncthreads();
}

// untangle pair (Zk, Zm) at frequency k -> multiply by (Kk, Km) -> retangle.
// Returns Ck; writes Cm via pointer.
__device__ __forceinline__ float2 conv_pair(float2 Zk, float2 Zm, float uc, float us,
                                            float4 kp, float2* Cm) {
    float2 Fe = make_float2(0.5f * (Zk.x + Zm.x), 0.5f * (Zk.y - Zm.y));
    float2 Fo = make_float2(0.5f * (Zk.y + Zm.y), -0.5f * (Zk.x - Zm.x));
    float2 P = make_float2(uc * Fo.x + us * Fo.y, uc * Fo.y - us * Fo.x);  // (uc,-us)*Fo
    float2 Ak = cadd(Fe, P);
    float2 Am = make_float2(Fe.x - P.x, -(Fe.y - P.y));
    float2 Yk = cmul(Ak, make_float2(kp.x, kp.y));
    float2 Ym = cmul(Am, make_float2(kp.z, kp.w));
    float2 Ge = make_float2(0.5f * (Yk.x + Ym.x), 0.5f * (Yk.y - Ym.y));
    float2 d2 = make_float2(0.5f * (Yk.x - Ym.x), 0.5f * (Yk.y + Ym.y));
    float2 Go = make_float2(uc * d2.x - us * d2.y, uc * d2.y + us * d2.x);  // (uc,us)*d2
    *Cm = make_float2(Ge.x + Go.y, Ge.y - Go.x);
    return make_float2(Ge.x - Go.y, -(Ge.y + Go.x));
}

// K-spectrum untangle -> write (K[k], K[M-k]) pair
__device__ __forceinline__ void kspec_step(int k, float uc, float us,
                                           const float2* s, float4* __restrict__ outp) {
    int km = (Mm - k) & (Mm - 1);
    float2 Zk = s[pad16(k)];
    float2 Zm = s[pad16(km)];
    float2 Fe = make_float2(0.5f * (Zk.x + Zm.x), 0.5f * (Zk.y - Zm.y));
    float2 Fo = make_float2(0.5f * (Zk.y + Zm.y), -0.5f * (Zk.x - Zm.x));
    float2 P = make_float2(uc * Fo.x + us * Fo.y, uc * Fo.y - us * Fo.x);
    float2 Ak = cadd(Fe, P);
    float2 Am = make_float2(Fe.x - P.x, -(Fe.y - P.y));
    outp[k] = make_float4(Ak.x, Ak.y, Am.x, Am.y);
}

// ---- 64x64 float4 transpose tile with XOR swizzle ----
__device__ __forceinline__ void trans_tile(const float* __restrict__ src, float* __restrict__ dst,
                                           int ldS, int ldD, int r0, int c0,
                                           int u, int step, float4* tile) {
    int c = u & 15;
    for (int l = u >> 4; l < 64; l += step) {
        const float4* p = (const float4*)(src + (size_t)(r0 + l) * ldS + c0) + c;
        tile[l * 16 + (c ^ (l >> 2))] = *p;
    }
    __syncthreads();
    const float* ts = (const float*)tile;
    int l4 = u & 15;
    for (int h = u >> 4; h < 64; h += step) {
        int col = (h >> 2) ^ l4;
        int base = l4 * 64;
        float4 o;
        o.x = ts[(base + col) * 4 + (h & 3)];
        o.y = ts[(base + 16 + col) * 4 + (h & 3)];
        o.z = ts[(base + 32 + col) * 4 + (h & 3)];
        o.w = ts[(base + 48 + col) * 4 + (h & 3)];
        *((float4*)(dst + (size_t)(c0 + h) * ldD + r0) + l4) = o;
    }
}

__global__ void kdummy() {}

// ---------------- Kernel 1: K-spectrum pairs + input transpose ----------------
__global__ void __launch_bounds__(512) kfront(const float* __restrict__ x,
                                              const float* __restrict__ kin) {
    __shared__ __align__(16) float2 sbuf[SBUF_N];
    int t = threadIdx.x;
    if (blockIdx.x < Hh) {
        int h = blockIdx.x;
        float2 w8 = tw_base<8>(t), w64 = tw_base<64>(t), w512 = tw_base<512>(t);
        const float2* row = (const float2*)(kin + (size_t)h * Ll);
        float2 v[8];
#pragma unroll
        for (int r = 0; r < 4; ++r) {
            float2 a = row[t + (r << 9)];
            a.x = copysignf(fmaxf(fabsf(a.x) - 0.1f, 0.0f), a.x);
            a.y = copysignf(fmaxf(fabsf(a.y) - 0.1f, 0.0f), a.y);
            v[r] = a;
        }
#pragma unroll
        for (int r = 4; r < 8; ++r) v[r] = make_float2(0.0f, 0.0f);
        fft4096_reg(v, t, sbuf, w8, w64, w512, true);
        store_natural(v, t, sbuf);
        float4* outp = g_KP + (size_t)h * KPSTRIDE;
#pragma unroll
        for (int i = 0; i < 4; ++i) {
            int k = t + (i << 9);
            float us, uc;
            sincospif((float)k * (1.0f / 4096.0f), &us, &uc);
            kspec_step(k, uc, us, sbuf, outp);
        }
        if (t == 0) kspec_step(2048, 0.0f, 1.0f, sbuf, outp);
    } else {
        int bid = blockIdx.x - Hh;
        int b = bid >> 10;
        int rem = bid & 1023;
        int l0 = (rem >> 4) << 6;
        int h0 = (rem & 15) << 6;
        float4* tile = (float4*)sbuf;
        trans_tile(x + (size_t)b * Ll * Hh, g_xt + (size_t)b * Hh * Ll,
                   Hh, Ll, l0, h0, t, 32, tile);
    }
}

// ---------------- Kernel 2: per-(b,h) FFT convolution, register middle ----------------
__global__ void __launch_bounds__(512, 2) kmain() {
    __shared__ __align__(16) float2 sbuf[SBUF_N];
    int row = blockIdx.x;            // b*H + h
    int h = row & (Hh - 1);
    int t = threadIdx.x;
    float2 w8 = tw_base<8>(t), w64 = tw_base<64>(t), w512 = tw_base<512>(t);
    const float4* KP = g_KP + (size_t)h * KPSTRIDE;
    float2* xrow = ((float2*)g_xt) + (size_t)row * (Ll / 2);

    float2 v[8];
#pragma unroll
    for (int r = 0; r < 4; ++r) v[r] = xrow[t + (r << 9)];   // z[n] = x[2n] + i x[2n+1]
#pragma unroll
    for (int r = 4; r < 8; ++r) v[r] = make_float2(0.0f, 0.0f);
    fft4096_reg(v, t, sbuf, w8, w64, w512, true);   // v[r] = Z[t + 512 r]

    // publish upper half (slots 2048..4095) + Z[0] for the k=0 pair
#pragma unroll
    for (int r = 4; r < 8; ++r) sbuf[pad16(t + (r << 9))] = v[r];
    if (t == 0) sbuf[0] = v[0];
    __syncthreads();

    // middle: k = t + 512 i in [0,2047]; Zk in regs, Zm from smem.
    // Slot m is read (Zm) then written (Cm) by the SAME thread -> no hazard.
#pragma unroll
    for (int i = 0; i < 4; ++i) {
        int k = t + (i << 9);
        int m = (Mm - k) & (Mm - 1);
        float us, uc;
        sincospif((float)k * (1.0f / 4096.0f), &us, &uc);
        float2 Zm = sbuf[pad16(m)];
        float2 Cm;
        v[i] = conv_pair(v[i], Zm, uc, us, __ldg(&KP[k]), &Cm);
        if (k != 0) sbuf[pad16(m)] = Cm;      // m in 2049..4095 (k=0 self-pair skipped)
    }
    if (t == 0) {                             // Nyquist k=2048: self-pair, own slot
        float2 Z = sbuf[pad16(2048)];
        float2 Cm;
        sbuf[pad16(2048)] = conv_pair(Z, Z, 0.0f, 1.0f, __ldg(&KP[2048]), &Cm);
    }
    __syncthreads();

    // gather upper half of C; lower half already in v[0..3]
#pragma unroll
    for (int r = 4; r < 8; ++r) v[r] = sbuf[pad16(t + (r << 9))];
    __syncthreads();

    // inverse via conj trick: y-packed = conj(FFT(C))/M
    fft4096_reg(v, t, sbuf, w8, w64, w512, false);
    const float invM = 1.0f / 4096.0f;
#pragma unroll
    for (int r = 0; r < 4; ++r) {             // first 4096 reals = 2048 complex
        int p = t + (r << 9);
        xrow[p] = make_float2(v[r].x * invM, -v[r].y * invM);
    }
}

// ---------------- Kernel 3: transpose yt -> out, fused D*x skip ----------------
__global__ void __launch_bounds__(256) ktrans_out(const float* __restrict__ x,
                                                  const float* __restrict__ Dv,
                                                  float* __restrict__ out) {
    __shared__ __align__(16) float4 tile[1024];
    int b = blockIdx.z;
    int h0 = blockIdx.x << 6, l0 = blockIdx.y << 6;
    const float* src = g_xt + (size_t)b * Hh * Ll;
    int u = threadIdx.x;
    int c = u & 15;
    for (int l = u >> 4; l < 64; l += 16) {
        const float4* p = (const float4*)(src + (size_t)(h0 + l) * Ll + l0) + c;
        tile[l * 16 + (c ^ (l >> 2))] = *p;
    }
    __syncthreads();
    const float* ts = (const float*)tile;
    int l4 = u & 15;
    float4 d = ((const float4*)Dv)[(h0 >> 2) + l4];
    const float* xb = x + (size_t)b * Ll * Hh;
    float* ob = out + (size_t)b * Ll * Hh;
    for (int lh = u >> 4; lh < 64; lh += 16) {
        int col = (lh >> 2) ^ l4;
        int base = l4 * 64;
        float4 o;
        o.x = ts[(base + col) * 4 + (lh & 3)];
        o.y = ts[(base + 16 + col) * 4 + (lh & 3)];
        o.z = ts[(base + 32 + col) * 4 + (lh & 3)];
        o.w = ts[(base + 48 + col) * 4 + (lh & 3)];
        size_t off = (size_t)(l0 + lh) * Hh + h0;
        float4 xv = *((const float4*)(xb + off) + l4);
        o.x = fmaf(d.x, xv.x, o.x);
        o.y = fmaf(d.y, xv.y, o.y);
        o.z = fmaf(d.z, xv.z, o.z);
        o.w = fmaf(d.w, xv.w, o.w);
        *((float4*)(ob + off) + l4) = o;
    }
}

extern "C" void kernel_launch(void* const* d_in, const int* in_sizes, int n_in,
                              void* d_out, int out_size) {
    const float* x   = (const float*)d_in[0];
    const float* ker = (const float*)d_in[1];
    const float* Dv  = (const float*)d_in[2];
    for (int i = 0; i < n_in; ++i) {
        if (in_sizes[i] == Bb * Ll * Hh)      x   = (const float*)d_in[i];
        else if (in_sizes[i] == Hh * Ll)      ker = (const float*)d_in[i];
        else if (in_sizes[i] == Hh)           Dv  = (const float*)d_in[i];
    }
    kdummy<<<1, 32>>>();
    kdummy<<<1, 32>>>();
    kfront<<<Hh + (Bb * (Ll / 64) * (Hh / 64)), 512>>>(x, ker);
    kmain<<<Bb * Hh, 512>>>();
    ktrans_out<<<dim3(Hh / 64, Ll / 64, Bb), 256>>>(x, Dv, (float*)d_out);
}

// round 6
// speedup vs baseline: 1.1868x; 1.0959x over previous
#include <cuda_runtime.h>
#include <math.h>

#define Bb 4
#define Ll 4096
#define Hh 1024
#define Mm 4096          // complex FFT size (packs 8192 reals)
#define KPSTRIDE 2056    // float4 per head: (K[k], K[M-k]) for k=0..2048, padded

__device__ __align__(16) float g_xt[(size_t)Bb * Hh * Ll];
__device__ __align__(16) float4 g_KP[(size_t)Hh * KPSTRIDE];

__device__ __forceinline__ int pad16(int i) { return i + (i >> 4); }
// XOR layout for the Ns=8 exchange: conflict-free on both its scatter and gather
__device__ __forceinline__ int sxor8(int i) { return i ^ (((i >> 6) & 1) << 3); }
#define SBUF_N 4352      // > pad16(4095)+1 = 4351 (sxor8 stays < 4096)

__device__ __forceinline__ float2 cadd(float2 a, float2 b) { return make_float2(a.x + b.x, a.y + b.y); }
__device__ __forceinline__ float2 csub(float2 a, float2 b) { return make_float2(a.x - b.x, a.y - b.y); }
__device__ __forceinline__ float2 cmul(float2 a, float2 b) {
    return make_float2(a.x * b.x - a.y * b.y, a.x * b.y + a.y * b.x);
}
__device__ __forceinline__ float2 mnegi(float2 a) { return make_float2(a.y, -a.x); }  // * -i

template <int Ns>
__device__ __forceinline__ float2 tw_base(int t) {
    int j = t & (Ns - 1);
    float sn, cs;
    sincospif((float)j * (1.0f / (4.0f * (float)Ns)), &sn, &cs);
    return make_float2(cs, -sn);
}

__device__ __forceinline__ void twiddle8(float2 v[8], float2 w1) {
    float2 w = w1;
    v[1] = cmul(v[1], w);
#pragma unroll
    for (int r = 2; r < 8; ++r) { w = cmul(w, w1); v[r] = cmul(v[r], w); }
}

__device__ __forceinline__ void fft8_tail(float2 v[8],
        float2 E0, float2 E1, float2 E2, float2 E3,
        float2 O0, float2 O1, float2 O2, float2 O3) {
    const float s = 0.70710678118654752440f;
    float2 W1 = make_float2(s * (O1.x + O1.y), s * (O1.y - O1.x));
    float2 W2 = mnegi(O2);
    float2 W3 = make_float2(s * (O3.y - O3.x), -s * (O3.x + O3.y));
    v[0] = cadd(E0, O0); v[4] = csub(E0, O0);
    v[1] = cadd(E1, W1); v[5] = csub(E1, W1);
    v[2] = cadd(E2, W2); v[6] = csub(E2, W2);
    v[3] = cadd(E3, W3); v[7] = csub(E3, W3);
}

__device__ __forceinline__ void fft8(float2 v[8]) {
    float2 e0a = cadd(v[0], v[4]), e0b = csub(v[0], v[4]);
    float2 e1a = cadd(v[2], v[6]), e1b = csub(v[2], v[6]);
    float2 E0 = cadd(e0a, e1a), E2 = csub(e0a, e1a);
    float2 m1 = mnegi(e1b);
    float2 E1 = cadd(e0b, m1), E3 = csub(e0b, m1);
    float2 o0a = cadd(v[1], v[5]), o0b = csub(v[1], v[5]);
    float2 o1a = cadd(v[3], v[7]), o1b = csub(v[3], v[7]);
    float2 O0 = cadd(o0a, o1a), O2 = csub(o0a, o1a);
    float2 m2 = mnegi(o1b);
    float2 O1 = cadd(o0b, m2), O3 = csub(o0b, m2);
    fft8_tail(v, E0, E1, E2, E3, O0, O1, O2, O3);
}

// radix-8 butterfly with v[4..7] == 0 (zero-padded input, first pass only)
__device__ __forceinline__ void fft8h(float2 v[8]) {
    float2 E0 = cadd(v[0], v[2]), E2 = csub(v[0], v[2]);
    float2 m1 = mnegi(v[2]);
    float2 E1 = cadd(v[0], m1), E3 = csub(v[0], m1);
    float2 O0 = cadd(v[1], v[3]), O2 = csub(v[1], v[3]);
    float2 m2 = mnegi(v[3]);
    float2 O1 = cadd(v[1], m2), O3 = csub(v[1], m2);
    fft8_tail(v, E0, E1, E2, E3, O0, O1, O2, O3);
}

// exchange with pad16 layout (conflict-free for Ns=1 and Ns=64)
template <int Ns>
__device__ __forceinline__ void exch(float2 v[8], int t, float2* s) {
    int idxD = ((t & ~(Ns - 1)) << 3) | (t & (Ns - 1));
#pragma unroll
    for (int r = 0; r < 8; ++r) s[pad16(idxD + r * Ns)] = v[r];
    __syncthreads();
#pragma unroll
    for (int r = 0; r < 8; ++r) v[r] = s[pad16(t + (r << 9))];
    __syncthreads();
}

// Ns=8 exchange with XOR layout (pad16 is 2-way conflicted on this scatter)
__device__ __forceinline__ void exch8x(float2 v[8], int t, float2* s) {
    int idxD = ((t & ~7) << 3) | (t & 7);
#pragma unroll
    for (int r = 0; r < 8; ++r) s[sxor8(idxD + r * 8)] = v[r];
    __syncthreads();
#pragma unroll
    for (int r = 0; r < 8; ++r) v[r] = s[sxor8(t + (r << 9))];
    __syncthreads();
}

// 4096-pt FFT. Last pass's exchange is identity -> regs end natural: v[r] = Z[t+512r]
__device__ __forceinline__ void fft4096_reg(float2 v[8], int t, float2* s,
                                            float2 w8, float2 w64, float2 w512, bool halfzero) {
    if (halfzero) fft8h(v); else fft8(v);
    exch<1>(v, t, s);
    twiddle8(v, w8);  fft8(v); exch8x(v, t, s);
    twiddle8(v, w64); fft8(v); exch<64>(v, t, s);
    twiddle8(v, w512); fft8(v);
}

__device__ __forceinline__ void store_natural(const float2 v[8], int t, float2* s) {
#pragma unroll
    for (int r = 0; r < 8; ++r) s[pad16(t + (r << 9))] = v[r];
    __syncthreads();
}

// untangle pair (Zk, Zm) at frequency k -> multiply by (Kk, Km) -> retangle.
__device__ __forceinline__ float2 conv_pair(float2 Zk, float2 Zm, float uc, float us,
                                            float4 kp, float2* Cm) {
    float2 Fe = make_float2(0.5f * (Zk.x + Zm.x), 0.5f * (Zk.y - Zm.y));
    float2 Fo = make_float2(0.5f * (Zk.y + Zm.y), -0.5f * (Zk.x - Zm.x));
    float2 P = make_float2(uc * Fo.x + us * Fo.y, uc * Fo.y - us * Fo.x);  // (uc,-us)*Fo
    float2 Ak = cadd(Fe, P);
    float2 Am = make_float2(Fe.x - P.x, -(Fe.y - P.y));
    float2 Yk = cmul(Ak, make_float2(kp.x, kp.y));
    float2 Ym = cmul(Am, make_float2(kp.z, kp.w));
    float2 Ge = make_float2(0.5f * (Yk.x + Ym.x), 0.5f * (Yk.y - Ym.y));
    float2 d2 = make_float2(0.5f * (Yk.x - Ym.x), 0.5f * (Yk.y + Ym.y));
    float2 Go = make_float2(uc * d2.x - us * d2.y, uc * d2.y + us * d2.x);  // (uc,us)*d2
    *Cm = make_float2(Ge.x + Go.y, Ge.y - Go.x);
    return make_float2(Ge.x - Go.y, -(Ge.y + Go.x));
}

// K-spectrum untangle -> write (K[k], K[M-k]) pair
__device__ __forceinline__ void kspec_step(int k, float uc, float us,
                                           const float2* s, float4* __restrict__ outp) {
    int km = (Mm - k) & (Mm - 1);
    float2 Zk = s[pad16(k)];
    float2 Zm = s[pad16(km)];
    float2 Fe = make_float2(0.5f * (Zk.x + Zm.x), 0.5f * (Zk.y - Zm.y));
    float2 Fo = make_float2(0.5f * (Zk.y + Zm.y), -0.5f * (Zk.x - Zm.x));
    float2 P = make_float2(uc * Fo.x + us * Fo.y, uc * Fo.y - us * Fo.x);
    float2 Ak = cadd(Fe, P);
    float2 Am = make_float2(Fe.x - P.x, -(Fe.y - P.y));
    outp[k] = make_float4(Ak.x, Ak.y, Am.x, Am.y);
}

// ---- 64x64 float4 transpose tile with XOR swizzle ----
__device__ __forceinline__ void trans_tile(const float* __restrict__ src, float* __restrict__ dst,
                                           int ldS, int ldD, int r0, int c0,
                                           int u, int step, float4* tile) {
    int c = u & 15;
    for (int l = u >> 4; l < 64; l += step) {
        const float4* p = (const float4*)(src + (size_t)(r0 + l) * ldS + c0) + c;
        tile[l * 16 + (c ^ (l >> 2))] = *p;
    }
    __syncthreads();
    const float* ts = (const float*)tile;
    int l4 = u & 15;
    for (int h = u >> 4; h < 64; h += step) {
        int col = (h >> 2) ^ l4;
        int base = l4 * 64;
        float4 o;
        o.x = ts[(base + col) * 4 + (h & 3)];
        o.y = ts[(base + 16 + col) * 4 + (h & 3)];
        o.z = ts[(base + 32 + col) * 4 + (h & 3)];
        o.w = ts[(base + 48 + col) * 4 + (h & 3)];
        *((float4*)(dst + (size_t)(c0 + h) * ldD + r0) + l4) = o;
    }
}

__global__ void kdummy() {}

// rotation by pi/8 (k advances by 512): exact constant-angle recurrence
#define C8 0.92387953251128675613f
#define S8 0.38268343236508977173f

// ---------------- Kernel 1: K-spectrum pairs + input transpose ----------------
__global__ void __launch_bounds__(512) kfront(const float* __restrict__ x,
                                              const float* __restrict__ kin) {
    __shared__ __align__(16) float2 sbuf[SBUF_N];
    int t = threadIdx.x;
    if (blockIdx.x < Hh) {
        int h = blockIdx.x;
        float2 w8 = tw_base<8>(t), w64 = tw_base<64>(t), w512 = tw_base<512>(t);
        const float2* row = (const float2*)(kin + (size_t)h * Ll);
        float2 v[8];
#pragma unroll
        for (int r = 0; r < 4; ++r) {
            float2 a = row[t + (r << 9)];
            a.x = copysignf(fmaxf(fabsf(a.x) - 0.1f, 0.0f), a.x);
            a.y = copysignf(fmaxf(fabsf(a.y) - 0.1f, 0.0f), a.y);
            v[r] = a;
        }
#pragma unroll
        for (int r = 4; r < 8; ++r) v[r] = make_float2(0.0f, 0.0f);
        fft4096_reg(v, t, sbuf, w8, w64, w512, true);
        store_natural(v, t, sbuf);
        float4* outp = g_KP + (size_t)h * KPSTRIDE;
        float us, uc;
        sincospif((float)t * (1.0f / 4096.0f), &us, &uc);
#pragma unroll
        for (int i = 0; i < 4; ++i) {
            kspec_step(t + (i << 9), uc, us, sbuf, outp);
            float nc = uc * C8 - us * S8;           // rotate angle by +pi/8
            us = us * C8 + uc * S8;
            uc = nc;
        }
        if (t == 0) kspec_step(2048, 0.0f, 1.0f, sbuf, outp);
    } else {
        int bid = blockIdx.x - Hh;
        int b = bid >> 10;
        int rem = bid & 1023;
        int l0 = (rem >> 4) << 6;
        int h0 = (rem & 15) << 6;
        float4* tile = (float4*)sbuf;
        trans_tile(x + (size_t)b * Ll * Hh, g_xt + (size_t)b * Hh * Ll,
                   Hh, Ll, l0, h0, t, 32, tile);
    }
}

// ---------------- Kernel 2: per-(b,h) FFT convolution, register middle ----------------
__global__ void __launch_bounds__(512, 2) kmain() {
    __shared__ __align__(16) float2 sbuf[SBUF_N];
    int row = blockIdx.x;            // b*H + h
    int h = row & (Hh - 1);
    int t = threadIdx.x;
    float2 w8 = tw_base<8>(t), w64 = tw_base<64>(t), w512 = tw_base<512>(t);
    const float4* KP = g_KP + (size_t)h * KPSTRIDE;
    float2* xrow = ((float2*)g_xt) + (size_t)row * (Ll / 2);

    float2 v[8];
#pragma unroll
    for (int r = 0; r < 4; ++r) v[r] = xrow[t + (r << 9)];   // z[n] = x[2n] + i x[2n+1]
#pragma unroll
    for (int r = 4; r < 8; ++r) v[r] = make_float2(0.0f, 0.0f);
    fft4096_reg(v, t, sbuf, w8, w64, w512, true);   // v[r] = Z[t + 512 r]

    // publish upper half (slots 2048..4095) + Z[0] for the k=0 pair
#pragma unroll
    for (int r = 4; r < 8; ++r) sbuf[pad16(t + (r << 9))] = v[r];
    if (t == 0) sbuf[0] = v[0];
    __syncthreads();

    // middle: k = t + 512 i in [0,2047]; Zk in regs, Zm from smem.
    // Slot m is read (Zm) then written (Cm) by the SAME thread -> no hazard.
    float us, uc;
    sincospif((float)t * (1.0f / 4096.0f), &us, &uc);
#pragma unroll
    for (int i = 0; i < 4; ++i) {
        int k = t + (i << 9);
        int m = (Mm - k) & (Mm - 1);
        float2 Zm = sbuf[pad16(m)];
        float2 Cm;
        v[i] = conv_pair(v[i], Zm, uc, us, __ldg(&KP[k]), &Cm);
        if (k != 0) sbuf[pad16(m)] = Cm;      // m in 2049..4095 (k=0 self-pair skipped)
        float nc = uc * C8 - us * S8;         // rotate angle by +pi/8
        us = us * C8 + uc * S8;
        uc = nc;
    }
    if (t == 0) {                             // Nyquist k=2048: self-pair, own slot
        float2 Z = sbuf[pad16(2048)];
        float2 Cm;
        sbuf[pad16(2048)] = conv_pair(Z, Z, 0.0f, 1.0f, __ldg(&KP[2048]), &Cm);
    }
    __syncthreads();

    // gather upper half of C; lower half already in v[0..3]
#pragma unroll
    for (int r = 4; r < 8; ++r) v[r] = sbuf[pad16(t + (r << 9))];
    __syncthreads();

    // inverse via conj trick: y-packed = conj(FFT(C))/M
    fft4096_reg(v, t, sbuf, w8, w64, w512, false);
    const float invM = 1.0f / 4096.0f;
#pragma unroll
    for (int r = 0; r < 4; ++r) {             // first 4096 reals = 2048 complex
        int p = t + (r << 9);
        xrow[p] = make_float2(v[r].x * invM, -v[r].y * invM);
    }
}

// ---------------- Kernel 3: transpose yt -> out, fused D*x skip ----------------
__global__ void __launch_bounds__(256) ktrans_out(const float* __restrict__ x,
                                                  const float* __restrict__ Dv,
                                                  float* __restrict__ out) {
    __shared__ __align__(16) float4 tile[1024];
    int b = blockIdx.z;
    int h0 = blockIdx.x << 6, l0 = blockIdx.y << 6;
    const float* src = g_xt + (size_t)b * Hh * Ll;
    int u = threadIdx.x;
    int c = u & 15;
    for (int l = u >> 4; l < 64; l += 16) {
        const float4* p = (const float4*)(src + (size_t)(h0 + l) * Ll + l0) + c;
        tile[l * 16 + (c ^ (l >> 2))] = *p;
    }
    __syncthreads();
    const float* ts = (const float*)tile;
    int l4 = u & 15;
    float4 d = ((const float4*)Dv)[(h0 >> 2) + l4];
    const float* xb = x + (size_t)b * Ll * Hh;
    float* ob = out + (size_t)b * Ll * Hh;
    for (int lh = u >> 4; lh < 64; lh += 16) {
        int col = (lh >> 2) ^ l4;
        int base = l4 * 64;
        float4 o;
        o.x = ts[(base + col) * 4 + (lh & 3)];
        o.y = ts[(base + 16 + col) * 4 + (lh & 3)];
        o.z = ts[(base + 32 + col) * 4 + (lh & 3)];
        o.w = ts[(base + 48 + col) * 4 + (lh & 3)];
        size_t off = (size_t)(l0 + lh) * Hh + h0;
        float4 xv = *((const float4*)(xb + off) + l4);
        o.x = fmaf(d.x, xv.x, o.x);
        o.y = fmaf(d.y, xv.y, o.y);
        o.z = fmaf(d.z, xv.z, o.z);
        o.w = fmaf(d.w, xv.w, o.w);
        *((float4*)(ob + off) + l4) = o;
    }
}

extern "C" void kernel_launch(void* const* d_in, const int* in_sizes, int n_in,
                              void* d_out, int out_size) {
    const float* x   = (const float*)d_in[0];
    const float* ker = (const float*)d_in[1];
    const float* Dv  = (const float*)d_in[2];
    for (int i = 0; i < n_in; ++i) {
        if (in_sizes[i] == Bb * Ll * Hh)      x   = (const float*)d_in[i];
        else if (in_sizes[i] == Hh * Ll)      ker = (const float*)d_in[i];
        else if (in_sizes[i] == Hh)           Dv  = (const float*)d_in[i];
    }
    kdummy<<<1, 32>>>();
    kdummy<<<1, 32>>>();
    kfront<<<Hh + (Bb * (Ll / 64) * (Hh / 64)), 512>>>(x, ker);
    kmain<<<Bb * Hh, 512>>>();
    ktrans_out<<<dim3(Hh / 64, Ll / 64, Bb), 256>>>(x, Dv, (float*)d_out);
}

// round 7
// speedup vs baseline: 1.2771x; 1.0761x over previous
#include <cuda_runtime.h>
#include <math.h>

#define Bb 4
#define Ll 4096
#define Hh 1024
#define Mm 4096          // complex FFT size (packs 8192 reals)
#define KPSTRIDE 2056    // float4 per head: (K[k], K[M-k]) for k=0..2048, padded

__device__ __align__(16) float g_xt[(size_t)Bb * Hh * Ll];
__device__ __align__(16) float4 g_KP[(size_t)Hh * KPSTRIDE];

__device__ __forceinline__ int pad16(int i) { return i + (i >> 4); }
// XOR layout for the Ns=8 exchange: conflict-free on both its scatter and gather
__device__ __forceinline__ int sxor8(int i) { return i ^ (((i >> 6) & 1) << 3); }
#define SBUF_N 4352      // > pad16(4095)+1 = 4351 (sxor8 stays < 4096)

__device__ __forceinline__ float2 cadd(float2 a, float2 b) { return make_float2(a.x + b.x, a.y + b.y); }
__device__ __forceinline__ float2 csub(float2 a, float2 b) { return make_float2(a.x - b.x, a.y - b.y); }
__device__ __forceinline__ float2 cmul(float2 a, float2 b) {
    return make_float2(a.x * b.x - a.y * b.y, a.x * b.y + a.y * b.x);
}

// ---------- packed f32x2 helpers (sm_103a) ----------
typedef unsigned long long p2;
__device__ __forceinline__ p2 pkf(float2 a) {
    p2 r; asm("mov.b64 %0, {%1, %2};" : "=l"(r) : "f"(a.x), "f"(a.y)); return r;
}
__device__ __forceinline__ float2 upk(p2 a) {
    float2 r; asm("mov.b64 {%0, %1}, %2;" : "=f"(r.x), "=f"(r.y) : "l"(a)); return r;
}
__device__ __forceinline__ p2 padd(p2 a, p2 b) {
    p2 r; asm("add.rn.f32x2 %0, %1, %2;" : "=l"(r) : "l"(a), "l"(b)); return r;
}
// a - b  ==  fma(b, (-1,-1), a)   (exact)
__device__ __forceinline__ p2 psub(p2 a, p2 b, p2 n1) {
    p2 r; asm("fma.rn.f32x2 %0, %1, %2, %3;" : "=l"(r) : "l"(b), "l"(n1), "l"(a)); return r;
}
__device__ __forceinline__ p2 negone2() {
    p2 r; asm("mov.b64 %0, 0xBF800000BF800000;" : "=l"(r)); return r;
}

// mixed packed/scalar tail of the radix-8 butterfly
__device__ __forceinline__ void fft8_tailp(float2 v[8],
        p2 E0, p2 E2, float2 E1, float2 E3,
        p2 O0, p2 O2, float2 O1, float2 O3, p2 n1) {
    const float s = 0.70710678118654752440f;
    float2 W1 = make_float2(s * (O1.x + O1.y), s * (O1.y - O1.x));
    float2 W3 = make_float2(s * (O3.y - O3.x), -s * (O3.x + O3.y));
    v[0] = upk(padd(E0, O0)); v[4] = upk(psub(E0, O0, n1));
    float2 E2f = upk(E2), O2f = upk(O2);
    v[2] = make_float2(E2f.x + O2f.y, E2f.y - O2f.x);   // E2 + (-i)O2
    v[6] = make_float2(E2f.x - O2f.y, E2f.y + O2f.x);
    v[1] = cadd(E1, W1); v[5] = csub(E1, W1);
    v[3] = cadd(E3, W3); v[7] = csub(E3, W3);
}

__device__ __forceinline__ void fft8(float2 v[8], p2 n1) {
    p2 a0 = pkf(v[0]), a1 = pkf(v[1]), a2 = pkf(v[2]), a3 = pkf(v[3]);
    p2 a4 = pkf(v[4]), a5 = pkf(v[5]), a6 = pkf(v[6]), a7 = pkf(v[7]);
    p2 e0a = padd(a0, a4), e0b = psub(a0, a4, n1);
    p2 e1a = padd(a2, a6), e1b = psub(a2, a6, n1);
    p2 o0a = padd(a1, a5), o0b = psub(a1, a5, n1);
    p2 o1a = padd(a3, a7), o1b = psub(a3, a7, n1);
    p2 E0 = padd(e0a, e1a), E2 = psub(e0a, e1a, n1);
    p2 O0 = padd(o0a, o1a), O2 = psub(o0a, o1a, n1);
    float2 f0 = upk(e0b), f1 = upk(e1b), g0 = upk(o0b), g1 = upk(o1b);
    float2 E1 = make_float2(f0.x + f1.y, f0.y - f1.x);   // e0b + (-i)e1b
    float2 E3 = make_float2(f0.x - f1.y, f0.y + f1.x);
    float2 O1 = make_float2(g0.x + g1.y, g0.y - g1.x);
    float2 O3 = make_float2(g0.x - g1.y, g0.y + g1.x);
    fft8_tailp(v, E0, E2, E1, E3, O0, O2, O1, O3, n1);
}

// radix-8 butterfly with v[4..7] == 0 (zero-padded input, first pass only)
__device__ __forceinline__ void fft8h(float2 v[8], p2 n1) {
    p2 a0 = pkf(v[0]), a1 = pkf(v[1]), a2 = pkf(v[2]), a3 = pkf(v[3]);
    p2 E0 = padd(a0, a2), E2 = psub(a0, a2, n1);
    p2 O0 = padd(a1, a3), O2 = psub(a1, a3, n1);
    float2 E1 = make_float2(v[0].x + v[2].y, v[0].y - v[2].x);
    float2 E3 = make_float2(v[0].x - v[2].y, v[0].y + v[2].x);
    float2 O1 = make_float2(v[1].x + v[3].y, v[1].y - v[3].x);
    float2 O3 = make_float2(v[1].x - v[3].y, v[1].y + v[3].x);
    fft8_tailp(v, E0, E2, E1, E3, O0, O2, O1, O3, n1);
}

template <int Ns>
__device__ __forceinline__ float2 tw_base(int t) {
    int j = t & (Ns - 1);
    float sn, cs;
    sincospif((float)j * (1.0f / (4.0f * (float)Ns)), &sn, &cs);
    return make_float2(cs, -sn);
}

// tree-structured twiddle: depth 3 instead of 6
__device__ __forceinline__ void twiddle8(float2 v[8], float2 w1) {
    float2 w2 = cmul(w1, w1);
    float2 w3 = cmul(w2, w1);
    float2 w4 = cmul(w2, w2);
    float2 w5 = cmul(w3, w2);
    float2 w6 = cmul(w3, w3);
    float2 w7 = cmul(w4, w3);
    v[1] = cmul(v[1], w1); v[2] = cmul(v[2], w2); v[3] = cmul(v[3], w3);
    v[4] = cmul(v[4], w4); v[5] = cmul(v[5], w5); v[6] = cmul(v[6], w6);
    v[7] = cmul(v[7], w7);
}

// exchange with pad16 layout (conflict-free for Ns=1 and Ns=64)
template <int Ns>
__device__ __forceinline__ void exch(float2 v[8], int t, float2* s) {
    int idxD = ((t & ~(Ns - 1)) << 3) | (t & (Ns - 1));
#pragma unroll
    for (int r = 0; r < 8; ++r) s[pad16(idxD + r * Ns)] = v[r];
    __syncthreads();
#pragma unroll
    for (int r = 0; r < 8; ++r) v[r] = s[pad16(t + (r << 9))];
    __syncthreads();
}

// Ns=8 exchange with XOR layout (pad16 is 2-way conflicted on this scatter)
__device__ __forceinline__ void exch8x(float2 v[8], int t, float2* s) {
    int idxD = ((t & ~7) << 3) | (t & 7);
#pragma unroll
    for (int r = 0; r < 8; ++r) s[sxor8(idxD + r * 8)] = v[r];
    __syncthreads();
#pragma unroll
    for (int r = 0; r < 8; ++r) v[r] = s[sxor8(t + (r << 9))];
    __syncthreads();
}

// 4096-pt FFT. Last pass's exchange is identity -> regs end natural: v[r] = Z[t+512r]
__device__ __forceinline__ void fft4096_reg(float2 v[8], int t, float2* s,
                                            float2 w8, float2 w64, float2 w512,
                                            bool halfzero, p2 n1) {
    if (halfzero) fft8h(v, n1); else fft8(v, n1);
    exch<1>(v, t, s);
    twiddle8(v, w8);  fft8(v, n1); exch8x(v, t, s);
    twiddle8(v, w64); fft8(v, n1); exch<64>(v, t, s);
    twiddle8(v, w512); fft8(v, n1);
}

__device__ __forceinline__ void store_natural(const float2 v[8], int t, float2* s) {
#pragma unroll
    for (int r = 0; r < 8; ++r) s[pad16(t + (r << 9))] = v[r];
    __syncthreads();
}

// untangle pair (Zk, Zm) at frequency k -> multiply by (Kk, Km) -> retangle.
__device__ __forceinline__ float2 conv_pair(float2 Zk, float2 Zm, float uc, float us,
                                            float4 kp, float2* Cm) {
    float2 Fe = make_float2(0.5f * (Zk.x + Zm.x), 0.5f * (Zk.y - Zm.y));
    float2 Fo = make_float2(0.5f * (Zk.y + Zm.y), -0.5f * (Zk.x - Zm.x));
    float2 P = make_float2(uc * Fo.x + us * Fo.y, uc * Fo.y - us * Fo.x);  // (uc,-us)*Fo
    float2 Ak = cadd(Fe, P);
    float2 Am = make_float2(Fe.x - P.x, -(Fe.y - P.y));
    float2 Yk = cmul(Ak, make_float2(kp.x, kp.y));
    float2 Ym = cmul(Am, make_float2(kp.z, kp.w));
    float2 Ge = make_float2(0.5f * (Yk.x + Ym.x), 0.5f * (Yk.y - Ym.y));
    float2 d2 = make_float2(0.5f * (Yk.x - Ym.x), 0.5f * (Yk.y + Ym.y));
    float2 Go = make_float2(uc * d2.x - us * d2.y, uc * d2.y + us * d2.x);  // (uc,us)*d2
    *Cm = make_float2(Ge.x + Go.y, Ge.y - Go.x);
    return make_float2(Ge.x - Go.y, -(Ge.y + Go.x));
}

// K-spectrum untangle -> write (K[k], K[M-k]) pair
__device__ __forceinline__ void kspec_step(int k, float uc, float us,
                                           const float2* s, float4* __restrict__ outp) {
    int km = (Mm - k) & (Mm - 1);
    float2 Zk = s[pad16(k)];
    float2 Zm = s[pad16(km)];
    float2 Fe = make_float2(0.5f * (Zk.x + Zm.x), 0.5f * (Zk.y - Zm.y));
    float2 Fo = make_float2(0.5f * (Zk.y + Zm.y), -0.5f * (Zk.x - Zm.x));
    float2 P = make_float2(uc * Fo.x + us * Fo.y, uc * Fo.y - us * Fo.x);
    float2 Ak = cadd(Fe, P);
    float2 Am = make_float2(Fe.x - P.x, -(Fe.y - P.y));
    outp[k] = make_float4(Ak.x, Ak.y, Am.x, Am.y);
}

// ---- 64x64 float4 transpose tile with XOR swizzle ----
__device__ __forceinline__ void trans_tile(const float* __restrict__ src, float* __restrict__ dst,
                                           int ldS, int ldD, int r0, int c0,
                                           int u, int step, float4* tile) {
    int c = u & 15;
    for (int l = u >> 4; l < 64; l += step) {
        const float4* p = (const float4*)(src + (size_t)(r0 + l) * ldS + c0) + c;
        tile[l * 16 + (c ^ (l >> 2))] = *p;
    }
    __syncthreads();
    const float* ts = (const float*)tile;
    int l4 = u & 15;
    for (int h = u >> 4; h < 64; h += step) {
        int col = (h >> 2) ^ l4;
        int base = l4 * 64;
        float4 o;
        o.x = ts[(base + col) * 4 + (h & 3)];
        o.y = ts[(base + 16 + col) * 4 + (h & 3)];
        o.z = ts[(base + 32 + col) * 4 + (h & 3)];
        o.w = ts[(base + 48 + col) * 4 + (h & 3)];
        *((float4*)(dst + (size_t)(c0 + h) * ldD + r0) + l4) = o;
    }
}

__global__ void kdummy() {}

// rotation by pi/8 (k advances by 512): exact constant-angle recurrence
#define C8 0.92387953251128675613f
#define S8 0.38268343236508977173f

// ---------------- Kernel 1: K-spectrum pairs + input transpose ----------------
__global__ void __launch_bounds__(512) kfront(const float* __restrict__ x,
                                              const float* __restrict__ kin) {
    __shared__ __align__(16) float2 sbuf[SBUF_N];
    int t = threadIdx.x;
    if (blockIdx.x < Hh) {
        int h = blockIdx.x;
        p2 n1 = negone2();
        float2 w8 = tw_base<8>(t), w64 = tw_base<64>(t), w512 = tw_base<512>(t);
        const float2* row = (const float2*)(kin + (size_t)h * Ll);
        float2 v[8];
#pragma unroll
        for (int r = 0; r < 4; ++r) {
            float2 a = row[t + (r << 9)];
            a.x = copysignf(fmaxf(fabsf(a.x) - 0.1f, 0.0f), a.x);
            a.y = copysignf(fmaxf(fabsf(a.y) - 0.1f, 0.0f), a.y);
            v[r] = a;
        }
#pragma unroll
        for (int r = 4; r < 8; ++r) v[r] = make_float2(0.0f, 0.0f);
        fft4096_reg(v, t, sbuf, w8, w64, w512, true, n1);
        store_natural(v, t, sbuf);
        float4* outp = g_KP + (size_t)h * KPSTRIDE;
        float us, uc;
        sincospif((float)t * (1.0f / 4096.0f), &us, &uc);
#pragma unroll
        for (int i = 0; i < 4; ++i) {
            kspec_step(t + (i << 9), uc, us, sbuf, outp);
            float nc = uc * C8 - us * S8;           // rotate angle by +pi/8
            us = us * C8 + uc * S8;
            uc = nc;
        }
        if (t == 0) kspec_step(2048, 0.0f, 1.0f, sbuf, outp);
    } else {
        int bid = blockIdx.x - Hh;
        int b = bid >> 10;
        int rem = bid & 1023;
        int l0 = (rem >> 4) << 6;
        int h0 = (rem & 15) << 6;
        float4* tile = (float4*)sbuf;
        trans_tile(x + (size_t)b * Ll * Hh, g_xt + (size_t)b * Hh * Ll,
                   Hh, Ll, l0, h0, t, 32, tile);
    }
}

// ---------------- Kernel 2: per-(b,h) FFT conv, register middle, fused skip ----------------
__global__ void __launch_bounds__(512, 2) kmain(const float* __restrict__ Dv) {
    __shared__ __align__(16) float2 sbuf[SBUF_N];
    int row = blockIdx.x;            // b*H + h
    int h = row & (Hh - 1);
    int t = threadIdx.x;
    p2 n1 = negone2();
    float dh = __ldg(&Dv[h]);
    float2 w8 = tw_base<8>(t), w64 = tw_base<64>(t), w512 = tw_base<512>(t);
    const float4* KP = g_KP + (size_t)h * KPSTRIDE;
    float2* xrow = ((float2*)g_xt) + (size_t)row * (Ll / 2);

    float2 v[8];
#pragma unroll
    for (int r = 0; r < 4; ++r) v[r] = xrow[t + (r << 9)];   // z[n] = x[2n] + i x[2n+1]
#pragma unroll
    for (int r = 4; r < 8; ++r) v[r] = make_float2(0.0f, 0.0f);
    fft4096_reg(v, t, sbuf, w8, w64, w512, true, n1);   // v[r] = Z[t + 512 r]

    // publish upper half (slots 2048..4095) + Z[0] for the k=0 pair
#pragma unroll
    for (int r = 4; r < 8; ++r) sbuf[pad16(t + (r << 9))] = v[r];
    if (t == 0) sbuf[0] = v[0];
    __syncthreads();

    // middle: k = t + 512 i in [0,2047]; Zk in regs, Zm from smem.
    float us, uc;
    sincospif((float)t * (1.0f / 4096.0f), &us, &uc);
#pragma unroll
    for (int i = 0; i < 4; ++i) {
        int k = t + (i << 9);
        int m = (Mm - k) & (Mm - 1);
        float2 Zm = sbuf[pad16(m)];
        float2 Cm;
        v[i] = conv_pair(v[i], Zm, uc, us, __ldg(&KP[k]), &Cm);
        if (k != 0) sbuf[pad16(m)] = Cm;      // m in 2049..4095 (k=0 self-pair skipped)
        float nc = uc * C8 - us * S8;         // rotate angle by +pi/8
        us = us * C8 + uc * S8;
        uc = nc;
    }
    if (t == 0) {                             // Nyquist k=2048: self-pair, own slot
        float2 Z = sbuf[pad16(2048)];
        float2 Cm;
        sbuf[pad16(2048)] = conv_pair(Z, Z, 0.0f, 1.0f, __ldg(&KP[2048]), &Cm);
    }
    __syncthreads();

    // gather upper half of C; lower half already in v[0..3]
#pragma unroll
    for (int r = 4; r < 8; ++r) v[r] = sbuf[pad16(t + (r << 9))];
    __syncthreads();

    // inverse via conj trick: y-packed = conj(FFT(C))/M ; fuse D*x skip (read-then-write,
    // same thread owns slot p, x row is L2-hot from the start-of-kernel read)
    fft4096_reg(v, t, sbuf, w8, w64, w512, false, n1);
    const float invM = 1.0f / 4096.0f;
#pragma unroll
    for (int r = 0; r < 4; ++r) {
        int p = t + (r << 9);
        float2 xv = xrow[p];
        xrow[p] = make_float2(fmaf(dh, xv.x, v[r].x * invM),
                              fmaf(dh, xv.y, -v[r].y * invM));
    }
}

// ---------------- Kernel 3: transpose yt [B,H,L] -> out [B,L,H] ----------------
__global__ void __launch_bounds__(256) ktrans_out(float* __restrict__ out) {
    __shared__ __align__(16) float4 tile[1024];
    int b = blockIdx.z;
    int h0 = blockIdx.x << 6, l0 = blockIdx.y << 6;
    trans_tile(g_xt + (size_t)b * Hh * Ll, out + (size_t)b * Ll * Hh,
               Ll, Hh, h0, l0, threadIdx.x, 16, tile);
}

extern "C" void kernel_launch(void* const* d_in, const int* in_sizes, int n_in,
                              void* d_out, int out_size) {
    const float* x   = (const float*)d_in[0];
    const float* ker = (const float*)d_in[1];
    const float* Dv  = (const float*)d_in[2];
    for (int i = 0; i < n_in; ++i) {
        if (in_sizes[i] == Bb * Ll * Hh)      x   = (const float*)d_in[i];
        else if (in_sizes[i] == Hh * Ll)      ker = (const float*)d_in[i];
        else if (in_sizes[i] == Hh)           Dv  = (const float*)d_in[i];
    }
    kdummy<<<1, 32>>>();
    kdummy<<<1, 32>>>();
    kfront<<<Hh + (Bb * (Ll / 64) * (Hh / 64)), 512>>>(x, ker);
    kmain<<<Bb * Hh, 512>>>(Dv);
    ktrans_out<<<dim3(Hh / 64, Ll / 64, Bb), 256>>>((float*)d_out);
}

// round 8
// speedup vs baseline: 1.2800x; 1.0023x over previous
#include <cuda_runtime.h>
#include <math.h>

#define Bb 4
#define Ll 4096
#define Hh 1024
#define Mm 4096          // complex FFT size (packs 8192 reals)
#define KPSTRIDE 2056    // float4 per head: (K[k], K[M-k]) for k=0..2048, padded

__device__ __align__(16) float g_xt[(size_t)Bb * Hh * Ll];
__device__ __align__(16) float4 g_KP[(size_t)Hh * KPSTRIDE];

__device__ __forceinline__ int pad16(int i) { return i + (i >> 4); }
// XOR layout for the Ns=8 exchange: conflict-free on both its scatter and gather
__device__ __forceinline__ int sxor8(int i) { return i ^ (((i >> 6) & 1) << 3); }
#define SBUF_N 4352                    // > pad16(4095)+1 = 4351
#define DSMEM_BYTES (2 * SBUF_N * 8)   // two float2 buffers (double-buffered exchanges)

__device__ __forceinline__ float2 cadd(float2 a, float2 b) { return make_float2(a.x + b.x, a.y + b.y); }
__device__ __forceinline__ float2 csub(float2 a, float2 b) { return make_float2(a.x - b.x, a.y - b.y); }
__device__ __forceinline__ float2 cmul(float2 a, float2 b) {
    return make_float2(a.x * b.x - a.y * b.y, a.x * b.y + a.y * b.x);
}

// ---------- packed f32x2 helpers (sm_103a) ----------
typedef unsigned long long p2;
__device__ __forceinline__ p2 pkf(float2 a) {
    p2 r; asm("mov.b64 %0, {%1, %2};" : "=l"(r) : "f"(a.x), "f"(a.y)); return r;
}
__device__ __forceinline__ float2 upk(p2 a) {
    float2 r; asm("mov.b64 {%0, %1}, %2;" : "=f"(r.x), "=f"(r.y) : "l"(a)); return r;
}
__device__ __forceinline__ p2 padd(p2 a, p2 b) {
    p2 r; asm("add.rn.f32x2 %0, %1, %2;" : "=l"(r) : "l"(a), "l"(b)); return r;
}
// a - b  ==  fma(b, (-1,-1), a)   (exact)
__device__ __forceinline__ p2 psub(p2 a, p2 b, p2 n1) {
    p2 r; asm("fma.rn.f32x2 %0, %1, %2, %3;" : "=l"(r) : "l"(b), "l"(n1), "l"(a)); return r;
}
__device__ __forceinline__ p2 negone2() {
    p2 r; asm("mov.b64 %0, 0xBF800000BF800000;" : "=l"(r)); return r;
}

// mixed packed/scalar tail of the radix-8 butterfly
__device__ __forceinline__ void fft8_tailp(float2 v[8],
        p2 E0, p2 E2, float2 E1, float2 E3,
        p2 O0, p2 O2, float2 O1, float2 O3, p2 n1) {
    const float s = 0.70710678118654752440f;
    float2 W1 = make_float2(s * (O1.x + O1.y), s * (O1.y - O1.x));
    float2 W3 = make_float2(s * (O3.y - O3.x), -s * (O3.x + O3.y));
    v[0] = upk(padd(E0, O0)); v[4] = upk(psub(E0, O0, n1));
    float2 E2f = upk(E2), O2f = upk(O2);
    v[2] = make_float2(E2f.x + O2f.y, E2f.y - O2f.x);   // E2 + (-i)O2
    v[6] = make_float2(E2f.x - O2f.y, E2f.y + O2f.x);
    v[1] = cadd(E1, W1); v[5] = csub(E1, W1);
    v[3] = cadd(E3, W3); v[7] = csub(E3, W3);
}

__device__ __forceinline__ void fft8(float2 v[8], p2 n1) {
    p2 a0 = pkf(v[0]), a1 = pkf(v[1]), a2 = pkf(v[2]), a3 = pkf(v[3]);
    p2 a4 = pkf(v[4]), a5 = pkf(v[5]), a6 = pkf(v[6]), a7 = pkf(v[7]);
    p2 e0a = padd(a0, a4), e0b = psub(a0, a4, n1);
    p2 e1a = padd(a2, a6), e1b = psub(a2, a6, n1);
    p2 o0a = padd(a1, a5), o0b = psub(a1, a5, n1);
    p2 o1a = padd(a3, a7), o1b = psub(a3, a7, n1);
    p2 E0 = padd(e0a, e1a), E2 = psub(e0a, e1a, n1);
    p2 O0 = padd(o0a, o1a), O2 = psub(o0a, o1a, n1);
    float2 f0 = upk(e0b), f1 = upk(e1b), g0 = upk(o0b), g1 = upk(o1b);
    float2 E1 = make_float2(f0.x + f1.y, f0.y - f1.x);   // e0b + (-i)e1b
    float2 E3 = make_float2(f0.x - f1.y, f0.y + f1.x);
    float2 O1 = make_float2(g0.x + g1.y, g0.y - g1.x);
    float2 O3 = make_float2(g0.x - g1.y, g0.y + g1.x);
    fft8_tailp(v, E0, E2, E1, E3, O0, O2, O1, O3, n1);
}

// radix-8 butterfly with v[4..7] == 0 (zero-padded input, first pass only)
__device__ __forceinline__ void fft8h(float2 v[8], p2 n1) {
    p2 a0 = pkf(v[0]), a1 = pkf(v[1]), a2 = pkf(v[2]), a3 = pkf(v[3]);
    p2 E0 = padd(a0, a2), E2 = psub(a0, a2, n1);
    p2 O0 = padd(a1, a3), O2 = psub(a1, a3, n1);
    float2 E1 = make_float2(v[0].x + v[2].y, v[0].y - v[2].x);
    float2 E3 = make_float2(v[0].x - v[2].y, v[0].y + v[2].x);
    float2 O1 = make_float2(v[1].x + v[3].y, v[1].y - v[3].x);
    float2 O3 = make_float2(v[1].x - v[3].y, v[1].y + v[3].x);
    fft8_tailp(v, E0, E2, E1, E3, O0, O2, O1, O3, n1);
}

template <int Ns>
__device__ __forceinline__ float2 tw_base(int t) {
    int j = t & (Ns - 1);
    float sn, cs;
    sincospif((float)j * (1.0f / (4.0f * (float)Ns)), &sn, &cs);
    return make_float2(cs, -sn);
}

// tree-structured twiddle: depth 3 instead of 6
__device__ __forceinline__ void twiddle8(float2 v[8], float2 w1) {
    float2 w2 = cmul(w1, w1);
    float2 w3 = cmul(w2, w1);
    float2 w4 = cmul(w2, w2);
    float2 w5 = cmul(w3, w2);
    float2 w6 = cmul(w3, w3);
    float2 w7 = cmul(w4, w3);
    v[1] = cmul(v[1], w1); v[2] = cmul(v[2], w2); v[3] = cmul(v[3], w3);
    v[4] = cmul(v[4], w4); v[5] = cmul(v[5], w5); v[6] = cmul(v[6], w6);
    v[7] = cmul(v[7], w7);
}

// Double-buffered exchange: ONE barrier per exchange. Caller alternates buffers;
// the alternation guarantees no scatter overwrites data a peer hasn't gathered.
template <int Ns>
__device__ __forceinline__ void exch_db(float2 v[8], int t, float2* s) {
    int idxD = ((t & ~(Ns - 1)) << 3) | (t & (Ns - 1));
#pragma unroll
    for (int r = 0; r < 8; ++r) s[pad16(idxD + r * Ns)] = v[r];
    __syncthreads();
#pragma unroll
    for (int r = 0; r < 8; ++r) v[r] = s[pad16(t + (r << 9))];
}

// Ns=8 exchange with XOR layout (pad16 is 2-way conflicted on this scatter)
__device__ __forceinline__ void exch8x_db(float2 v[8], int t, float2* s) {
    int idxD = ((t & ~7) << 3) | (t & 7);
#pragma unroll
    for (int r = 0; r < 8; ++r) s[sxor8(idxD + r * 8)] = v[r];
    __syncthreads();
#pragma unroll
    for (int r = 0; r < 8; ++r) v[r] = s[sxor8(t + (r << 9))];
}

// 4096-pt FFT, double-buffered (3 barriers). Buffers: s0, s1, s0.
// Exit: regs natural, v[r] = Z[t + 512 r]. Last gather was from s0.
__device__ __forceinline__ void fft4096_reg(float2 v[8], int t, float2* s0, float2* s1,
                                            float2 w8, float2 w64, float2 w512,
                                            bool halfzero, p2 n1) {
    if (halfzero) fft8h(v, n1); else fft8(v, n1);
    exch_db<1>(v, t, s0);
    twiddle8(v, w8);  fft8(v, n1); exch8x_db(v, t, s1);
    twiddle8(v, w64); fft8(v, n1); exch_db<64>(v, t, s0);
    twiddle8(v, w512); fft8(v, n1);
}

// untangle pair (Zk, Zm) at frequency k -> multiply by (Kk, Km) -> retangle.
__device__ __forceinline__ float2 conv_pair(float2 Zk, float2 Zm, float uc, float us,
                                            float4 kp, float2* Cm) {
    float2 Fe = make_float2(0.5f * (Zk.x + Zm.x), 0.5f * (Zk.y - Zm.y));
    float2 Fo = make_float2(0.5f * (Zk.y + Zm.y), -0.5f * (Zk.x - Zm.x));
    float2 P = make_float2(uc * Fo.x + us * Fo.y, uc * Fo.y - us * Fo.x);  // (uc,-us)*Fo
    float2 Ak = cadd(Fe, P);
    float2 Am = make_float2(Fe.x - P.x, -(Fe.y - P.y));
    float2 Yk = cmul(Ak, make_float2(kp.x, kp.y));
    float2 Ym = cmul(Am, make_float2(kp.z, kp.w));
    float2 Ge = make_float2(0.5f * (Yk.x + Ym.x), 0.5f * (Yk.y - Ym.y));
    float2 d2 = make_float2(0.5f * (Yk.x - Ym.x), 0.5f * (Yk.y + Ym.y));
    float2 Go = make_float2(uc * d2.x - us * d2.y, uc * d2.y + us * d2.x);  // (uc,us)*d2
    *Cm = make_float2(Ge.x + Go.y, Ge.y - Go.x);
    return make_float2(Ge.x - Go.y, -(Ge.y + Go.x));
}

// K-spectrum untangle -> write (K[k], K[M-k]) pair
__device__ __forceinline__ void kspec_step(int k, float uc, float us,
                                           const float2* s, float4* __restrict__ outp) {
    int km = (Mm - k) & (Mm - 1);
    float2 Zk = s[pad16(k)];
    float2 Zm = s[pad16(km)];
    float2 Fe = make_float2(0.5f * (Zk.x + Zm.x), 0.5f * (Zk.y - Zm.y));
    float2 Fo = make_float2(0.5f * (Zk.y + Zm.y), -0.5f * (Zk.x - Zm.x));
    float2 P = make_float2(uc * Fo.x + us * Fo.y, uc * Fo.y - us * Fo.x);
    float2 Ak = cadd(Fe, P);
    float2 Am = make_float2(Fe.x - P.x, -(Fe.y - P.y));
    outp[k] = make_float4(Ak.x, Ak.y, Am.x, Am.y);
}

// ---- 64x64 float4 transpose tile with XOR swizzle ----
__device__ __forceinline__ void trans_tile(const float* __restrict__ src, float* __restrict__ dst,
                                           int ldS, int ldD, int r0, int c0,
                                           int u, int step, float4* tile) {
    int c = u & 15;
    for (int l = u >> 4; l < 64; l += step) {
        const float4* p = (const float4*)(src + (size_t)(r0 + l) * ldS + c0) + c;
        tile[l * 16 + (c ^ (l >> 2))] = *p;
    }
    __syncthreads();
    const float* ts = (const float*)tile;
    int l4 = u & 15;
    for (int h = u >> 4; h < 64; h += step) {
        int col = (h >> 2) ^ l4;
        int base = l4 * 64;
        float4 o;
        o.x = ts[(base + col) * 4 + (h & 3)];
        o.y = ts[(base + 16 + col) * 4 + (h & 3)];
        o.z = ts[(base + 32 + col) * 4 + (h & 3)];
        o.w = ts[(base + 48 + col) * 4 + (h & 3)];
        *((float4*)(dst + (size_t)(c0 + h) * ldD + r0) + l4) = o;
    }
}

__global__ void kdummy() {}

// rotation by pi/8 (k advances by 512): exact constant-angle recurrence
#define C8 0.92387953251128675613f
#define S8 0.38268343236508977173f

// ---------------- Kernel 1: K-spectrum pairs + input transpose ----------------
__global__ void __launch_bounds__(512) kfront(const float* __restrict__ x,
                                              const float* __restrict__ kin) {
    extern __shared__ __align__(16) float2 dynbuf[];
    float2* s0 = dynbuf;
    float2* s1 = dynbuf + SBUF_N;
    int t = threadIdx.x;
    if (blockIdx.x < Hh) {
        int h = blockIdx.x;
        p2 n1 = negone2();
        float2 w8 = tw_base<8>(t), w64 = tw_base<64>(t), w512 = tw_base<512>(t);
        const float2* row = (const float2*)(kin + (size_t)h * Ll);
        float2 v[8];
#pragma unroll
        for (int r = 0; r < 4; ++r) {
            float2 a = row[t + (r << 9)];
            a.x = copysignf(fmaxf(fabsf(a.x) - 0.1f, 0.0f), a.x);
            a.y = copysignf(fmaxf(fabsf(a.y) - 0.1f, 0.0f), a.y);
            v[r] = a;
        }
#pragma unroll
        for (int r = 4; r < 8; ++r) v[r] = make_float2(0.0f, 0.0f);
        fft4096_reg(v, t, s0, s1, w8, w64, w512, true, n1);
        // publish natural-order Z into s1 (last gathered buffer was s0; s1's readers
        // all finished before the exch<64> barrier)
#pragma unroll
        for (int r = 0; r < 8; ++r) s1[pad16(t + (r << 9))] = v[r];
        __syncthreads();
        float4* outp = g_KP + (size_t)h * KPSTRIDE;
        float us, uc;
        sincospif((float)t * (1.0f / 4096.0f), &us, &uc);
#pragma unroll
        for (int i = 0; i < 4; ++i) {
            kspec_step(t + (i << 9), uc, us, s1, outp);
            float nc = uc * C8 - us * S8;           // rotate angle by +pi/8
            us = us * C8 + uc * S8;
            uc = nc;
        }
        if (t == 0) kspec_step(2048, 0.0f, 1.0f, s1, outp);
    } else {
        int bid = blockIdx.x - Hh;
        int b = bid >> 10;
        int rem = bid & 1023;
        int l0 = (rem >> 4) << 6;
        int h0 = (rem & 15) << 6;
        float4* tile = (float4*)dynbuf;
        trans_tile(x + (size_t)b * Ll * Hh, g_xt + (size_t)b * Hh * Ll,
                   Hh, Ll, l0, h0, t, 32, tile);
    }
}

// ---------------- Kernel 2: per-(b,h) FFT conv, double-buffered, fused skip ----------------
__global__ void __launch_bounds__(512, 2) kmain(const float* __restrict__ Dv) {
    extern __shared__ __align__(16) float2 dynbuf[];
    float2* s0 = dynbuf;
    float2* s1 = dynbuf + SBUF_N;
    int row = blockIdx.x;            // b*H + h
    int h = row & (Hh - 1);
    int t = threadIdx.x;
    p2 n1 = negone2();
    float dh = __ldg(&Dv[h]);
    float2 w8 = tw_base<8>(t), w64 = tw_base<64>(t), w512 = tw_base<512>(t);
    const float4* KP = g_KP + (size_t)h * KPSTRIDE;
    float2* xrow = ((float2*)g_xt) + (size_t)row * (Ll / 2);

    float2 v[8];
#pragma unroll
    for (int r = 0; r < 4; ++r) v[r] = xrow[t + (r << 9)];   // z[n] = x[2n] + i x[2n+1]
#pragma unroll
    for (int r = 4; r < 8; ++r) v[r] = make_float2(0.0f, 0.0f);
    fft4096_reg(v, t, s0, s1, w8, w64, w512, true, n1);   // v[r] = Z[t + 512 r]

    // publish upper half (slots 2048..4095) + Z[0] into s1; s1's exch8x readers all
    // finished before the exch<64> barrier -> no extra barrier before these writes
#pragma unroll
    for (int r = 4; r < 8; ++r) s1[pad16(t + (r << 9))] = v[r];
    if (t == 0) s1[0] = v[0];
    __syncthreads();

    // middle: k = t + 512 i in [0,2047]; Zk in regs, Zm from s1 (read+write same thread)
    float us, uc;
    sincospif((float)t * (1.0f / 4096.0f), &us, &uc);
#pragma unroll
    for (int i = 0; i < 4; ++i) {
        int k = t + (i << 9);
        int m = (Mm - k) & (Mm - 1);
        float2 Zm = s1[pad16(m)];
        float2 Cm;
        v[i] = conv_pair(v[i], Zm, uc, us, __ldg(&KP[k]), &Cm);
        if (k != 0) s1[pad16(m)] = Cm;        // m in 2049..4095 (k=0 self-pair skipped)
        float nc = uc * C8 - us * S8;         // rotate angle by +pi/8
        us = us * C8 + uc * S8;
        uc = nc;
    }
    if (t == 0) {                             // Nyquist k=2048: self-pair, own slot
        float2 Z = s1[pad16(2048)];
        float2 Cm;
        s1[pad16(2048)] = conv_pair(Z, Z, 0.0f, 1.0f, __ldg(&KP[2048]), &Cm);
    }
    __syncthreads();

    // gather upper half of C from s1; lower half already in v[0..3]. The inverse FFT's
    // first scatter goes to s0 (safe: s0's readers finished before the publish barrier)
#pragma unroll
    for (int r = 4; r < 8; ++r) v[r] = s1[pad16(t + (r << 9))];

    // inverse via conj trick: y-packed = conj(FFT(C))/M ; fuse D*x skip
    fft4096_reg(v, t, s0, s1, w8, w64, w512, false, n1);
    const float invM = 1.0f / 4096.0f;
#pragma unroll
    for (int r = 0; r < 4; ++r) {
        int p = t + (r << 9);
        float2 xv = xrow[p];
        xrow[p] = make_float2(fmaf(dh, xv.x, v[r].x * invM),
                              fmaf(dh, xv.y, -v[r].y * invM));
    }
}

// ---------------- Kernel 3: transpose yt [B,H,L] -> out [B,L,H] ----------------
__global__ void __launch_bounds__(256) ktrans_out(float* __restrict__ out) {
    __shared__ __align__(16) float4 tile[1024];
    int b = blockIdx.z;
    int h0 = blockIdx.x << 6, l0 = blockIdx.y << 6;
    trans_tile(g_xt + (size_t)b * Hh * Ll, out + (size_t)b * Ll * Hh,
               Ll, Hh, h0, l0, threadIdx.x, 16, tile);
}

extern "C" void kernel_launch(void* const* d_in, const int* in_sizes, int n_in,
                              void* d_out, int out_size) {
    const float* x   = (const float*)d_in[0];
    const float* ker = (const float*)d_in[1];
    const float* Dv  = (const float*)d_in[2];
    for (int i = 0; i < n_in; ++i) {
        if (in_sizes[i] == Bb * Ll * Hh)      x   = (const float*)d_in[i];
        else if (in_sizes[i] == Hh * Ll)      ker = (const float*)d_in[i];
        else if (in_sizes[i] == Hh)           Dv  = (const float*)d_in[i];
    }
    // Attribute persists on the function after the first (pre-capture) call, so the
    // captured launches are covered even if this call is a no-op during capture.
    cudaFuncSetAttribute(kfront, cudaFuncAttributeMaxDynamicSharedMemorySize, DSMEM_BYTES);
    cudaFuncSetAttribute(kmain,  cudaFuncAttributeMaxDynamicSharedMemorySize, DSMEM_BYTES);
    kdummy<<<1, 32>>>();
    kdummy<<<1, 32>>>();
    kfront<<<Hh + (Bb * (Ll / 64) * (Hh / 64)), 512, DSMEM_BYTES>>>(x, ker);
    kmain<<<Bb * Hh, 512, DSMEM_BYTES>>>(Dv);
    ktrans_out<<<dim3(Hh / 64, Ll / 64, Bb), 256>>>((float*)d_out);
}